// round 14
// baseline (speedup 1.0000x reference)
#include <cuda_runtime.h>
#include <math.h>

#define NPIX 50176
#define CF   4224
#define NS   128
#define DH   1024
#define PPB  392
#define ROWQ (CF / 4)
#define SEGCAP 768

// ---------------- scratch ----------------------------------------------------
__device__ int   g_hist[NS];
__device__ int   g_off[NS + 1];
__device__ int   g_bh[NS * NS];
__device__ int   g_bcls[NS * NS * 3];
__device__ int   g_perm[NPIX];
__device__ int   g_lab[NS];
__device__ float g_feat[NS * CF];
__device__ float g_G[NS * NS];
__device__ float g_h1[NS * DH];
__device__ float g_h2[NS * DH];
__device__ int   g_bar0;
__device__ int   g_bar1;
__device__ int   g_flag4;    // gemm2 blocks done (target 128)

// ---------------- helpers ----------------------------------------------------
__device__ __forceinline__ unsigned long long pack_dup(float a) {
    unsigned long long r;
    asm("mov.b64 %0, {%1, %1};" : "=l"(r) : "f"(a));
    return r;
}
__device__ __forceinline__ void fma2(unsigned long long& acc,
                                     unsigned long long a,
                                     unsigned long long b) {
    asm("fma.rn.f32x2 %0, %1, %2, %0;" : "+l"(acc) : "l"(a), "l"(b));
}
__device__ __forceinline__ void unpack2(unsigned long long v, float& lo, float& hi) {
    asm("mov.b64 {%0, %1}, %2;" : "=f"(lo), "=f"(hi) : "l"(v));
}
__device__ __forceinline__ void red4(float* p, float a, float b, float c, float d) {
    asm volatile("red.global.add.v4.f32 [%0], {%1, %2, %3, %4};"
                 :: "l"(p), "f"(a), "f"(b), "f"(c), "f"(d) : "memory");
}
__device__ __forceinline__ void spin_for(const int* flag, int target) {
    if (threadIdx.x == 0) {
        while (*(volatile const int*)flag < target) __nanosleep(64);
    }
    __syncthreads();
    __threadfence();
}

// ---------------- K1: prep (hist + meta + scatter + zero) -------------------
__global__ void __launch_bounds__(256) k_prep(const int* __restrict__ sp,
                                              const int* __restrict__ y) {
    __shared__ int sh[NS];
    __shared__ int sc[NS * 3];
    __shared__ int cur[NS];
    int b = blockIdx.x;
    int tid = threadIdx.x;

    if (b == 0 && tid == 0) g_flag4 = 0;   // replay-deterministic reset

    for (int i = tid; i < NS; i += 256) sh[i] = 0;
    for (int i = tid; i < NS * 3; i += 256) sc[i] = 0;
    __syncthreads();
    int base = b * PPB;
    int s0 = sp[base + tid];
    int s1 = sp[base + 256 + ((tid < PPB - 256) ? tid : 0)];
    int y0 = y[base + tid];
    int y1 = y[base + 256 + ((tid < PPB - 256) ? tid : 0)];
    atomicAdd(&sh[s0], 1);
    atomicAdd(&sc[s0 * 3 + y0], 1);
    if (tid < PPB - 256) {
        atomicAdd(&sh[s1], 1);
        atomicAdd(&sc[s1 * 3 + y1], 1);
    }
    __syncthreads();
    for (int i = tid; i < NS; i += 256) g_bh[b * NS + i] = sh[i];
    for (int i = tid; i < NS * 3; i += 256) g_bcls[b * NS * 3 + i] = sc[i];

    float4 z = make_float4(0.f, 0.f, 0.f, 0.f);
    ((float4*)g_h1)[b * 256 + tid] = z;
    ((float4*)g_h2)[b * 256 + tid] = z;
    if (tid < 32) ((float4*)g_G)[b * 32 + tid] = z;

    __threadfence();
    __syncthreads();
    if (tid == 0) {
        atomicAdd(&g_bar0, 1);
        while (*(volatile int*)&g_bar0 < NS) { }
    }
    __syncthreads();

    __shared__ int off_sh[NS];
    __shared__ int tot_sh[NS];
    __shared__ int pre_sh[NS];
    if (tid < NS) {
        int s = tid;
        int tot = 0, pre = 0;
        for (int bb = 0; bb < NS; bb++) {
            int v = g_bh[bb * NS + s];
            if (bb < b) pre += v;
            tot += v;
        }
        tot_sh[s] = tot;
        pre_sh[s] = pre;
        if (b == 0) {
            g_hist[s] = tot;
            int c0 = 0, c1 = 0, c2 = 0;
            for (int bb = 0; bb < NS; bb++) {
                c0 += g_bcls[bb * NS * 3 + s * 3 + 0];
                c1 += g_bcls[bb * NS * 3 + s * 3 + 1];
                c2 += g_bcls[bb * NS * 3 + s * 3 + 2];
            }
            int lab = (c1 > c0) ? ((c2 > c1) ? 2 : 1) : ((c2 > c0) ? 2 : 0);
            if (lab == 0) lab = (c2 > (tot >> 1)) ? 2 : ((c1 >= 1) ? 1 : 0);
            g_lab[s] = lab;
        }
    }
    __syncthreads();
    if (tid == 0) {
        int a = 0;
        for (int i = 0; i < NS; i++) { off_sh[i] = a; a += tot_sh[i]; }
        if (b == 0) {
            for (int i = 0; i < NS; i++) g_off[i] = off_sh[i];
            g_off[NS] = a;
        }
    }
    __syncthreads();
    if (tid < NS) cur[tid] = off_sh[tid] + pre_sh[tid];
    __syncthreads();

    {
        int p = atomicAdd(&cur[s0], 1);
        g_perm[p] = base + tid;
        if (tid < PPB - 256) {
            int q = atomicAdd(&cur[s1], 1);
            g_perm[q] = base + 256 + tid;
        }
    }

    __threadfence();
    __syncthreads();
    if (tid == 0) {
        int v = atomicAdd(&g_bar1, 1);
        if (v == NS - 1) { g_bar0 = 0; g_bar1 = 0; }
    }
}

// ---------------- K1b: no-op (keeps gemm1_gram in the ncu window) -----------
__global__ void k_nop() {
    if (blockIdx.x == 0 && threadIdx.x == 0) g_bar0 = 0;  // already 0
}

// ---------------- K2: segment mean (~84% DRAM; unchanged) -------------------
__global__ void __launch_bounds__(256) k_segsum(const float* __restrict__ pix) {
    int ct = blockIdx.x;
    int s  = blockIdx.y;
    int tx = threadIdx.x & 31;
    int ty = threadIdx.x >> 5;
    int beg = g_off[s], end = g_off[s + 1];
    int n = end - beg;

    __shared__ int sidx[SEGCAP];
    int cap = n < SEGCAP ? n : SEGCAP;
    for (int i = threadIdx.x; i < cap; i += 256) sidx[i] = g_perm[beg + i];
    __syncthreads();

    const float4* __restrict__ p4 = (const float4*)pix;
    int colq = ct * 32 + tx;

    float4 A0 = make_float4(0.f, 0.f, 0.f, 0.f);
    float4 A1 = make_float4(0.f, 0.f, 0.f, 0.f);
    float4 A2 = make_float4(0.f, 0.f, 0.f, 0.f);
    float4 A3 = make_float4(0.f, 0.f, 0.f, 0.f);

    int r = ty;
    for (; r + 56 < cap; r += 64) {
        float4 v0 = __ldcs(p4 + (size_t)sidx[r]      * ROWQ + colq);
        float4 v1 = __ldcs(p4 + (size_t)sidx[r +  8] * ROWQ + colq);
        float4 v2 = __ldcs(p4 + (size_t)sidx[r + 16] * ROWQ + colq);
        float4 v3 = __ldcs(p4 + (size_t)sidx[r + 24] * ROWQ + colq);
        float4 v4 = __ldcs(p4 + (size_t)sidx[r + 32] * ROWQ + colq);
        float4 v5 = __ldcs(p4 + (size_t)sidx[r + 40] * ROWQ + colq);
        float4 v6 = __ldcs(p4 + (size_t)sidx[r + 48] * ROWQ + colq);
        float4 v7 = __ldcs(p4 + (size_t)sidx[r + 56] * ROWQ + colq);
        A0.x += v0.x; A0.y += v0.y; A0.z += v0.z; A0.w += v0.w;
        A1.x += v1.x; A1.y += v1.y; A1.z += v1.z; A1.w += v1.w;
        A2.x += v2.x; A2.y += v2.y; A2.z += v2.z; A2.w += v2.w;
        A3.x += v3.x; A3.y += v3.y; A3.z += v3.z; A3.w += v3.w;
        A0.x += v4.x; A0.y += v4.y; A0.z += v4.z; A0.w += v4.w;
        A1.x += v5.x; A1.y += v5.y; A1.z += v5.z; A1.w += v5.w;
        A2.x += v6.x; A2.y += v6.y; A2.z += v6.z; A2.w += v6.w;
        A3.x += v7.x; A3.y += v7.y; A3.z += v7.z; A3.w += v7.w;
    }
    for (; r < cap; r += 8) {
        float4 v0 = __ldcs(p4 + (size_t)sidx[r] * ROWQ + colq);
        A0.x += v0.x; A0.y += v0.y; A0.z += v0.z; A0.w += v0.w;
    }
    for (int r2 = SEGCAP + ty; r2 < n; r2 += 8) {
        float4 v0 = __ldcs(p4 + (size_t)g_perm[beg + r2] * ROWQ + colq);
        A0.x += v0.x; A0.y += v0.y; A0.z += v0.z; A0.w += v0.w;
    }
    A0.x += A1.x + A2.x + A3.x;
    A0.y += A1.y + A2.y + A3.y;
    A0.z += A1.z + A2.z + A3.z;
    A0.w += A1.w + A2.w + A3.w;

    __shared__ float4 red[8][32];
    red[ty][tx] = A0;
    __syncthreads();
    if (ty == 0) {
        float4 t = red[0][tx];
        #pragma unroll
        for (int w = 1; w < 8; w++) {
            t.x += red[w][tx].x; t.y += red[w][tx].y;
            t.z += red[w][tx].z; t.w += red[w][tx].w;
        }
        float c = (float)max(n, 1);
        t.x /= c; t.y /= c; t.z /= c; t.w /= c;
        *(float4*)&g_feat[s * CF + colq * 4] = t;
    }
}

// ---------------- K3: gemm1 (384 blocks, kchunk 176) + gram (66) ------------
// A staged into smem PRE-DUPLICATED as f32x2 -> inner loop has zero pack movs.
__global__ void __launch_bounds__(256) k_gemm1_gram(const float* __restrict__ B) {
    int blk = blockIdx.x;
    int tid = threadIdx.x;

    if (blk >= 384) {
        // ---- gram: G += feat_chunk @ feat_chunk^T ----
        __shared__ float Gs[64][129];
        int kc = blk - 384;  // 0..65
        {
            int k  = tid & 63;
            int io = tid >> 6;
            #pragma unroll 8
            for (int p = 0; p < 32; p++) {
                int i = p * 4 + io;
                Gs[k][i] = g_feat[i * CF + kc * 64 + k];
            }
        }
        __syncthreads();
        int tx = tid & 15, ty = tid >> 4;
        float acc[8][8];
        #pragma unroll
        for (int m = 0; m < 8; m++)
            #pragma unroll
            for (int n = 0; n < 8; n++) acc[m][n] = 0.f;
        for (int kk = 0; kk < 64; kk++) {
            float a[8], b[8];
            #pragma unroll
            for (int m = 0; m < 8; m++) a[m] = Gs[kk][ty * 8 + m];
            #pragma unroll
            for (int n = 0; n < 8; n++) b[n] = Gs[kk][tx * 8 + n];
            #pragma unroll
            for (int m = 0; m < 8; m++)
                #pragma unroll
                for (int n = 0; n < 8; n++) acc[m][n] += a[m] * b[n];
        }
        #pragma unroll
        for (int m = 0; m < 8; m++) {
            float* dst = &g_G[(ty * 8 + m) * NS + tx * 8];
            red4(dst,     acc[m][0], acc[m][1], acc[m][2], acc[m][3]);
            red4(dst + 4, acc[m][4], acc[m][5], acc[m][6], acc[m][7]);
        }
        return;
    }

    // ---- gemm1: h1 += feat @ w1; 16 ntiles x 24 kchunks of 176 ----
    const int KCHUNK = 176;
    int ntile = blk & 15;
    int k0 = (blk >> 4) * KCHUNK;

    __shared__ unsigned long long As2[16][133];  // duplicated f32x2, padded
    __shared__ float Bs[16][68];
    int tx = tid & 15, ty = tid >> 4;
    int bk = tid >> 6;       // 0..3
    int bn = tid & 63;

    unsigned long long acc[8][2];
    #pragma unroll
    for (int m = 0; m < 8; m++) { acc[m][0] = 0ull; acc[m][1] = 0ull; }

    float ra[8], rb[4];
    #pragma unroll
    for (int p = 0; p < 8; p++)
        ra[p] = g_feat[(ty + p * 16) * CF + k0 + tx];
    #pragma unroll
    for (int p = 0; p < 4; p++)
        rb[p] = B[(k0 + p * 4 + bk) * DH + ntile * 64 + bn];

    for (int kt = 0; kt < KCHUNK; kt += 16) {
        #pragma unroll
        for (int p = 0; p < 8; p++) As2[tx][ty + p * 16] = pack_dup(ra[p]);
        #pragma unroll
        for (int p = 0; p < 4; p++) Bs[p * 4 + bk][bn] = rb[p];
        __syncthreads();
        if (kt + 16 < KCHUNK) {   // prefetch next slab during compute
            int kg = k0 + kt + 16;
            #pragma unroll
            for (int p = 0; p < 8; p++)
                ra[p] = g_feat[(ty + p * 16) * CF + kg + tx];
            #pragma unroll
            for (int p = 0; p < 4; p++)
                rb[p] = B[(kg + p * 4 + bk) * DH + ntile * 64 + bn];
        }
        #pragma unroll
        for (int kk = 0; kk < 16; kk++) {
            ulonglong2 bv = *(const ulonglong2*)&Bs[kk][tx * 4];
            #pragma unroll
            for (int m = 0; m < 8; m++) {
                unsigned long long aa = As2[kk][ty * 8 + m];  // LDS.64 broadcast
                fma2(acc[m][0], aa, bv.x);
                fma2(acc[m][1], aa, bv.y);
            }
        }
        __syncthreads();
    }
    #pragma unroll
    for (int m = 0; m < 8; m++) {
        int r = ty * 8 + m;
        int n = ntile * 64 + tx * 4;
        float l0, h0, l1, h1v;
        unpack2(acc[m][0], l0, h0);
        unpack2(acc[m][1], l1, h1v);
        red4(&g_h1[r * DH + n], l0, h0, l1, h1v);
    }
}

// ---------------- K4: gemm2 (128) + labels (1) + tail (128), ONE launch -----
__global__ void __launch_bounds__(256) k_gemm2_tail(const float* __restrict__ B,
                               const float* __restrict__ bias,
                               const float* __restrict__ b2,
                               const float* __restrict__ w3,
                               const float* __restrict__ b3,
                               const float* __restrict__ wc,
                               const float* __restrict__ bc,
                               float* __restrict__ out) {
    int blk = blockIdx.x;
    int tid = threadIdx.x;

    if (blk == 128) {
        // ---- label propagation ----
        __shared__ float nrm[NS];
        __shared__ int   labsh[NS];
        int i = tid;
        if (i < NS) {
            labsh[i] = g_lab[i];
            nrm[i] = rsqrtf(g_G[i * NS + i]);
        }
        __syncthreads();
        if (i < NS) {
            float maxv = -__int_as_float(0x7f800000);
            int best = 0;
            float ni = nrm[i];
            for (int j = 0; j < NS; j++) {
                if (labsh[j] != 0) {
                    float a = g_G[i * NS + j] * ni * nrm[j];
                    if (a > maxv) { maxv = a; best = j; }
                }
            }
            int lab = labsh[i];
            if (lab == 0 && maxv > 0.8f) lab = labsh[best];
            out[256 + i] = (float)lab;
        }
        return;
    }

    if (blk > 128) {
        // ---- tail: h3 = relu(h2+b2)@w3, head, softmax (after gemm2) ----
        spin_for(&g_flag4, 128);
        int i = blk - 129;
        int j = tid & 31;
        int g = tid >> 5;
        const float* __restrict__ h2r = g_h2 + i * DH;
        float a0 = 0.f, a1 = 0.f;
        int kbase = g * 128;
        #pragma unroll 4
        for (int kk = 0; kk < 128; kk += 2) {
            int k = kbase + kk;
            a0 += fmaxf(h2r[k] + b2[k], 0.f) * w3[k * 32 + j];
            a1 += fmaxf(h2r[k + 1] + b2[k + 1], 0.f) * w3[(k + 1) * 32 + j];
        }
        __shared__ float red2[8][32];
        red2[g][j] = a0 + a1;
        __syncthreads();
        if (tid < 32) {
            float tot = red2[0][j];
            #pragma unroll
            for (int gg = 1; gg < 8; gg++) tot += red2[gg][j];
            float h = fmaxf(tot + b3[j], 0.f);
            float p0 = h * wc[j * 2 + 0];
            float p1 = h * wc[j * 2 + 1];
            #pragma unroll
            for (int o = 16; o > 0; o >>= 1) {
                p0 += __shfl_xor_sync(0xffffffff, p0, o);
                p1 += __shfl_xor_sync(0xffffffff, p1, o);
            }
            if (j == 0) {
                float l0 = p0 + bc[0], l1 = p1 + bc[1];
                float m = fmaxf(l0, l1);
                float e0 = expf(l0 - m), e1 = expf(l1 - m);
                float s = e0 + e1;
                out[i * 2 + 0] = e0 / s;
                out[i * 2 + 1] = e1 / s;
            }
        }
        return;
    }

    // ---- gemm2: h2 += relu(h1+b1) @ w2; 16 ntiles x 8 kchunks of 128 ----
    const int KCHUNK = 128;
    int ntile = blk & 15;
    int k0 = (blk >> 4) * KCHUNK;

    __shared__ unsigned long long As2[16][133];
    __shared__ float Bs[16][68];
    int tx = tid & 15, ty = tid >> 4;
    int bk = tid >> 6;
    int bn = tid & 63;

    unsigned long long acc[8][2];
    #pragma unroll
    for (int m = 0; m < 8; m++) { acc[m][0] = 0ull; acc[m][1] = 0ull; }

    float ra[8], rb[4];
    #pragma unroll
    for (int p = 0; p < 8; p++) {
        int kg = k0 + tx;
        ra[p] = fmaxf(g_h1[(ty + p * 16) * DH + kg] + bias[kg], 0.f);
    }
    #pragma unroll
    for (int p = 0; p < 4; p++)
        rb[p] = B[(k0 + p * 4 + bk) * DH + ntile * 64 + bn];

    for (int kt = 0; kt < KCHUNK; kt += 16) {
        #pragma unroll
        for (int p = 0; p < 8; p++) As2[tx][ty + p * 16] = pack_dup(ra[p]);
        #pragma unroll
        for (int p = 0; p < 4; p++) Bs[p * 4 + bk][bn] = rb[p];
        __syncthreads();
        if (kt + 16 < KCHUNK) {
            int kg = k0 + kt + 16;
            #pragma unroll
            for (int p = 0; p < 8; p++)
                ra[p] = fmaxf(g_h1[(ty + p * 16) * DH + kg + tx] + bias[kg + tx], 0.f);
            #pragma unroll
            for (int p = 0; p < 4; p++)
                rb[p] = B[(kg + p * 4 + bk) * DH + ntile * 64 + bn];
        }
        #pragma unroll
        for (int kk = 0; kk < 16; kk++) {
            ulonglong2 bv = *(const ulonglong2*)&Bs[kk][tx * 4];
            #pragma unroll
            for (int m = 0; m < 8; m++) {
                unsigned long long aa = As2[kk][ty * 8 + m];
                fma2(acc[m][0], aa, bv.x);
                fma2(acc[m][1], aa, bv.y);
            }
        }
        __syncthreads();
    }
    #pragma unroll
    for (int m = 0; m < 8; m++) {
        int r = ty * 8 + m;
        int n = ntile * 64 + tx * 4;
        float l0, h0, l1, h1v;
        unpack2(acc[m][0], l0, h0);
        unpack2(acc[m][1], l1, h1v);
        red4(&g_h2[r * DH + n], l0, h0, l1, h1v);
    }
    __threadfence();
    __syncthreads();
    if (tid == 0) atomicAdd(&g_flag4, 1);
}

// ---------------- launch ------------------------------------------------------
extern "C" void kernel_launch(void* const* d_in, const int* in_sizes, int n_in,
                              void* d_out, int out_size) {
    const float* pixfeat = (const float*)d_in[0];
    const float* w1 = (const float*)d_in[1];
    const float* b1 = (const float*)d_in[2];
    const float* w2 = (const float*)d_in[3];
    const float* b2 = (const float*)d_in[4];
    const float* w3 = (const float*)d_in[5];
    const float* b3 = (const float*)d_in[6];
    const float* wc = (const float*)d_in[7];
    const float* bc = (const float*)d_in[8];
    const int*   sp = (const int*)d_in[9];
    const int*   yy = (const int*)d_in[10];
    float* out = (float*)d_out;  // [0,256): probs, [256,384): lab

    k_prep<<<NS, 256>>>(sp, yy);                          // 1
    k_nop<<<1, 32>>>();                                   // 2 (window shim)
    k_segsum<<<dim3(33, NS), 256>>>(pixfeat);             // 3
    k_gemm1_gram<<<450, 256>>>(w1);                       // 4 <- profiled
    k_gemm2_tail<<<257, 256>>>(w2, b1, b2, w3, b3, wc, bc, out);  // 5
}

// round 15
// speedup vs baseline: 1.0347x; 1.0347x over previous
#include <cuda_runtime.h>
#include <math.h>

#define NPIX 50176
#define CF   4224
#define NS   128
#define DH   1024
#define PPB  392
#define ROWQ (CF / 4)
#define SEGCAP 768

// ---------------- scratch ----------------------------------------------------
__device__ int   g_hist[NS];
__device__ int   g_off[NS + 1];
__device__ int   g_bh[NS * NS];
__device__ int   g_bcls[NS * NS * 3];
__device__ int   g_perm[NPIX];
__device__ int   g_lab[NS];
__device__ float g_feat[NS * CF];
__device__ float g_G[NS * NS];
__device__ float g_h1[NS * DH];
__device__ float g_h2[NS * DH];
__device__ int   g_bar0;
__device__ int   g_bar1;
__device__ int   g_flag4;    // gemm2 blocks done (target 128)

// ---------------- helpers ----------------------------------------------------
__device__ __forceinline__ unsigned long long pack_dup(float a) {
    unsigned long long r;
    asm("mov.b64 %0, {%1, %1};" : "=l"(r) : "f"(a));
    return r;
}
__device__ __forceinline__ void fma2(unsigned long long& acc,
                                     unsigned long long a,
                                     unsigned long long b) {
    asm("fma.rn.f32x2 %0, %1, %2, %0;" : "+l"(acc) : "l"(a), "l"(b));
}
__device__ __forceinline__ void unpack2(unsigned long long v, float& lo, float& hi) {
    asm("mov.b64 {%0, %1}, %2;" : "=f"(lo), "=f"(hi) : "l"(v));
}
__device__ __forceinline__ void red4(float* p, float a, float b, float c, float d) {
    asm volatile("red.global.add.v4.f32 [%0], {%1, %2, %3, %4};"
                 :: "l"(p), "f"(a), "f"(b), "f"(c), "f"(d) : "memory");
}
__device__ __forceinline__ void spin_for(const int* flag, int target) {
    if (threadIdx.x == 0) {
        while (*(volatile const int*)flag < target) __nanosleep(64);
    }
    __syncthreads();
    __threadfence();
}

// ---------------- K1: prep (hist + meta + scatter + zero) -------------------
__global__ void __launch_bounds__(256) k_prep(const int* __restrict__ sp,
                                              const int* __restrict__ y) {
    __shared__ int sh[NS];
    __shared__ int sc[NS * 3];
    __shared__ int cur[NS];
    int b = blockIdx.x;
    int tid = threadIdx.x;

    if (b == 0 && tid == 0) g_flag4 = 0;   // replay-deterministic reset

    for (int i = tid; i < NS; i += 256) sh[i] = 0;
    for (int i = tid; i < NS * 3; i += 256) sc[i] = 0;
    __syncthreads();
    int base = b * PPB;
    int s0 = sp[base + tid];
    int s1 = sp[base + 256 + ((tid < PPB - 256) ? tid : 0)];
    int y0 = y[base + tid];
    int y1 = y[base + 256 + ((tid < PPB - 256) ? tid : 0)];
    atomicAdd(&sh[s0], 1);
    atomicAdd(&sc[s0 * 3 + y0], 1);
    if (tid < PPB - 256) {
        atomicAdd(&sh[s1], 1);
        atomicAdd(&sc[s1 * 3 + y1], 1);
    }
    __syncthreads();
    for (int i = tid; i < NS; i += 256) g_bh[b * NS + i] = sh[i];
    for (int i = tid; i < NS * 3; i += 256) g_bcls[b * NS * 3 + i] = sc[i];

    float4 z = make_float4(0.f, 0.f, 0.f, 0.f);
    ((float4*)g_h1)[b * 256 + tid] = z;
    ((float4*)g_h2)[b * 256 + tid] = z;
    if (tid < 32) ((float4*)g_G)[b * 32 + tid] = z;

    __threadfence();
    __syncthreads();
    if (tid == 0) {
        atomicAdd(&g_bar0, 1);
        while (*(volatile int*)&g_bar0 < NS) { }
    }
    __syncthreads();

    __shared__ int off_sh[NS];
    __shared__ int tot_sh[NS];
    __shared__ int pre_sh[NS];
    if (tid < NS) {
        int s = tid;
        int tot = 0, pre = 0;
        for (int bb = 0; bb < NS; bb++) {
            int v = g_bh[bb * NS + s];
            if (bb < b) pre += v;
            tot += v;
        }
        tot_sh[s] = tot;
        pre_sh[s] = pre;
        if (b == 0) {
            g_hist[s] = tot;
            int c0 = 0, c1 = 0, c2 = 0;
            for (int bb = 0; bb < NS; bb++) {
                c0 += g_bcls[bb * NS * 3 + s * 3 + 0];
                c1 += g_bcls[bb * NS * 3 + s * 3 + 1];
                c2 += g_bcls[bb * NS * 3 + s * 3 + 2];
            }
            int lab = (c1 > c0) ? ((c2 > c1) ? 2 : 1) : ((c2 > c0) ? 2 : 0);
            if (lab == 0) lab = (c2 > (tot >> 1)) ? 2 : ((c1 >= 1) ? 1 : 0);
            g_lab[s] = lab;
        }
    }
    __syncthreads();
    if (tid == 0) {
        int a = 0;
        for (int i = 0; i < NS; i++) { off_sh[i] = a; a += tot_sh[i]; }
        if (b == 0) {
            for (int i = 0; i < NS; i++) g_off[i] = off_sh[i];
            g_off[NS] = a;
        }
    }
    __syncthreads();
    if (tid < NS) cur[tid] = off_sh[tid] + pre_sh[tid];
    __syncthreads();

    {
        int p = atomicAdd(&cur[s0], 1);
        g_perm[p] = base + tid;
        if (tid < PPB - 256) {
            int q = atomicAdd(&cur[s1], 1);
            g_perm[q] = base + 256 + tid;
        }
    }

    __threadfence();
    __syncthreads();
    if (tid == 0) {
        int v = atomicAdd(&g_bar1, 1);
        if (v == NS - 1) { g_bar0 = 0; g_bar1 = 0; }
    }
}

// ---------------- K2: segment mean (~84% DRAM; unchanged) -------------------
__global__ void __launch_bounds__(256) k_segsum(const float* __restrict__ pix) {
    int ct = blockIdx.x;
    int s  = blockIdx.y;
    int tx = threadIdx.x & 31;
    int ty = threadIdx.x >> 5;
    int beg = g_off[s], end = g_off[s + 1];
    int n = end - beg;

    __shared__ int sidx[SEGCAP];
    int cap = n < SEGCAP ? n : SEGCAP;
    for (int i = threadIdx.x; i < cap; i += 256) sidx[i] = g_perm[beg + i];
    __syncthreads();

    const float4* __restrict__ p4 = (const float4*)pix;
    int colq = ct * 32 + tx;

    float4 A0 = make_float4(0.f, 0.f, 0.f, 0.f);
    float4 A1 = make_float4(0.f, 0.f, 0.f, 0.f);
    float4 A2 = make_float4(0.f, 0.f, 0.f, 0.f);
    float4 A3 = make_float4(0.f, 0.f, 0.f, 0.f);

    int r = ty;
    for (; r + 56 < cap; r += 64) {
        float4 v0 = __ldcs(p4 + (size_t)sidx[r]      * ROWQ + colq);
        float4 v1 = __ldcs(p4 + (size_t)sidx[r +  8] * ROWQ + colq);
        float4 v2 = __ldcs(p4 + (size_t)sidx[r + 16] * ROWQ + colq);
        float4 v3 = __ldcs(p4 + (size_t)sidx[r + 24] * ROWQ + colq);
        float4 v4 = __ldcs(p4 + (size_t)sidx[r + 32] * ROWQ + colq);
        float4 v5 = __ldcs(p4 + (size_t)sidx[r + 40] * ROWQ + colq);
        float4 v6 = __ldcs(p4 + (size_t)sidx[r + 48] * ROWQ + colq);
        float4 v7 = __ldcs(p4 + (size_t)sidx[r + 56] * ROWQ + colq);
        A0.x += v0.x; A0.y += v0.y; A0.z += v0.z; A0.w += v0.w;
        A1.x += v1.x; A1.y += v1.y; A1.z += v1.z; A1.w += v1.w;
        A2.x += v2.x; A2.y += v2.y; A2.z += v2.z; A2.w += v2.w;
        A3.x += v3.x; A3.y += v3.y; A3.z += v3.z; A3.w += v3.w;
        A0.x += v4.x; A0.y += v4.y; A0.z += v4.z; A0.w += v4.w;
        A1.x += v5.x; A1.y += v5.y; A1.z += v5.z; A1.w += v5.w;
        A2.x += v6.x; A2.y += v6.y; A2.z += v6.z; A2.w += v6.w;
        A3.x += v7.x; A3.y += v7.y; A3.z += v7.z; A3.w += v7.w;
    }
    for (; r < cap; r += 8) {
        float4 v0 = __ldcs(p4 + (size_t)sidx[r] * ROWQ + colq);
        A0.x += v0.x; A0.y += v0.y; A0.z += v0.z; A0.w += v0.w;
    }
    for (int r2 = SEGCAP + ty; r2 < n; r2 += 8) {
        float4 v0 = __ldcs(p4 + (size_t)g_perm[beg + r2] * ROWQ + colq);
        A0.x += v0.x; A0.y += v0.y; A0.z += v0.z; A0.w += v0.w;
    }
    A0.x += A1.x + A2.x + A3.x;
    A0.y += A1.y + A2.y + A3.y;
    A0.z += A1.z + A2.z + A3.z;
    A0.w += A1.w + A2.w + A3.w;

    __shared__ float4 red[8][32];
    red[ty][tx] = A0;
    __syncthreads();
    if (ty == 0) {
        float4 t = red[0][tx];
        #pragma unroll
        for (int w = 1; w < 8; w++) {
            t.x += red[w][tx].x; t.y += red[w][tx].y;
            t.z += red[w][tx].z; t.w += red[w][tx].w;
        }
        float c = (float)max(n, 1);
        t.x /= c; t.y /= c; t.z /= c; t.w /= c;
        *(float4*)&g_feat[s * CF + colq * 4] = t;
    }
}

// ---------------- K3: gemm1 (384 blocks, kchunk 176, dbl-buf) + gram (66) ---
// Exact R12 configuration (measured 37.0us).
__global__ void __launch_bounds__(256) k_gemm1_gram(const float* __restrict__ B) {
    int blk = blockIdx.x;
    int tid = threadIdx.x;

    if (blk >= 384) {
        // ---- gram: G += feat_chunk @ feat_chunk^T ----
        __shared__ float Gs[64][129];
        int kc = blk - 384;  // 0..65
        {
            int k  = tid & 63;
            int io = tid >> 6;
            #pragma unroll 8
            for (int p = 0; p < 32; p++) {
                int i = p * 4 + io;
                Gs[k][i] = g_feat[i * CF + kc * 64 + k];
            }
        }
        __syncthreads();
        int tx = tid & 15, ty = tid >> 4;
        float acc[8][8];
        #pragma unroll
        for (int m = 0; m < 8; m++)
            #pragma unroll
            for (int n = 0; n < 8; n++) acc[m][n] = 0.f;
        for (int kk = 0; kk < 64; kk++) {
            float a[8], b[8];
            #pragma unroll
            for (int m = 0; m < 8; m++) a[m] = Gs[kk][ty * 8 + m];
            #pragma unroll
            for (int n = 0; n < 8; n++) b[n] = Gs[kk][tx * 8 + n];
            #pragma unroll
            for (int m = 0; m < 8; m++)
                #pragma unroll
                for (int n = 0; n < 8; n++) acc[m][n] += a[m] * b[n];
        }
        #pragma unroll
        for (int m = 0; m < 8; m++) {
            float* dst = &g_G[(ty * 8 + m) * NS + tx * 8];
            red4(dst,     acc[m][0], acc[m][1], acc[m][2], acc[m][3]);
            red4(dst + 4, acc[m][4], acc[m][5], acc[m][6], acc[m][7]);
        }
        return;
    }

    // ---- gemm1: h1 += feat @ w1; 16 ntiles x 24 kchunks of 176 ----
    const int KCHUNK = 176;
    int ntile = blk & 15;
    int k0 = (blk >> 4) * KCHUNK;

    __shared__ float As[16][132];
    __shared__ float Bs[16][68];
    int tx = tid & 15, ty = tid >> 4;
    int bk = tid >> 6;       // 0..3
    int bn = tid & 63;

    unsigned long long acc[8][2];
    #pragma unroll
    for (int m = 0; m < 8; m++) { acc[m][0] = 0ull; acc[m][1] = 0ull; }

    float ra[8], rb[4];
    #pragma unroll
    for (int p = 0; p < 8; p++)
        ra[p] = g_feat[(ty + p * 16) * CF + k0 + tx];
    #pragma unroll
    for (int p = 0; p < 4; p++)
        rb[p] = B[(k0 + p * 4 + bk) * DH + ntile * 64 + bn];

    for (int kt = 0; kt < KCHUNK; kt += 16) {
        #pragma unroll
        for (int p = 0; p < 8; p++) As[tx][ty + p * 16] = ra[p];
        #pragma unroll
        for (int p = 0; p < 4; p++) Bs[p * 4 + bk][bn] = rb[p];
        __syncthreads();
        if (kt + 16 < KCHUNK) {   // prefetch next slab during compute
            int kg = k0 + kt + 16;
            #pragma unroll
            for (int p = 0; p < 8; p++)
                ra[p] = g_feat[(ty + p * 16) * CF + kg + tx];
            #pragma unroll
            for (int p = 0; p < 4; p++)
                rb[p] = B[(kg + p * 4 + bk) * DH + ntile * 64 + bn];
        }
        #pragma unroll
        for (int kk = 0; kk < 16; kk++) {
            float4 a0 = *(const float4*)&As[kk][ty * 8];
            float4 a1 = *(const float4*)&As[kk][ty * 8 + 4];
            ulonglong2 bv = *(const ulonglong2*)&Bs[kk][tx * 4];
            float am[8] = {a0.x, a0.y, a0.z, a0.w, a1.x, a1.y, a1.z, a1.w};
            #pragma unroll
            for (int m = 0; m < 8; m++) {
                unsigned long long aa = pack_dup(am[m]);
                fma2(acc[m][0], aa, bv.x);
                fma2(acc[m][1], aa, bv.y);
            }
        }
        __syncthreads();
    }
    #pragma unroll
    for (int m = 0; m < 8; m++) {
        int r = ty * 8 + m;
        int n = ntile * 64 + tx * 4;
        float l0, h0, l1, h1v;
        unpack2(acc[m][0], l0, h0);
        unpack2(acc[m][1], l1, h1v);
        red4(&g_h1[r * DH + n], l0, h0, l1, h1v);
    }
}

// ---------------- K4: gemm2 (128) + labels (1) + tail (128), ONE launch -----
__global__ void __launch_bounds__(256) k_gemm2_tail(const float* __restrict__ B,
                               const float* __restrict__ bias,
                               const float* __restrict__ b2,
                               const float* __restrict__ w3,
                               const float* __restrict__ b3,
                               const float* __restrict__ wc,
                               const float* __restrict__ bc,
                               float* __restrict__ out) {
    int blk = blockIdx.x;
    int tid = threadIdx.x;

    if (blk == 128) {
        // ---- label propagation ----
        __shared__ float nrm[NS];
        __shared__ int   labsh[NS];
        int i = tid;
        if (i < NS) {
            labsh[i] = g_lab[i];
            nrm[i] = rsqrtf(g_G[i * NS + i]);
        }
        __syncthreads();
        if (i < NS) {
            float maxv = -__int_as_float(0x7f800000);
            int best = 0;
            float ni = nrm[i];
            for (int j = 0; j < NS; j++) {
                if (labsh[j] != 0) {
                    float a = g_G[i * NS + j] * ni * nrm[j];
                    if (a > maxv) { maxv = a; best = j; }
                }
            }
            int lab = labsh[i];
            if (lab == 0 && maxv > 0.8f) lab = labsh[best];
            out[256 + i] = (float)lab;
        }
        return;
    }

    if (blk > 128) {
        // ---- tail: h3 = relu(h2+b2)@w3, head, softmax (after gemm2) ----
        spin_for(&g_flag4, 128);
        int i = blk - 129;
        int j = tid & 31;
        int g = tid >> 5;
        const float* __restrict__ h2r = g_h2 + i * DH;
        float a0 = 0.f, a1 = 0.f;
        int kbase = g * 128;
        #pragma unroll 4
        for (int kk = 0; kk < 128; kk += 2) {
            int k = kbase + kk;
            a0 += fmaxf(h2r[k] + b2[k], 0.f) * w3[k * 32 + j];
            a1 += fmaxf(h2r[k + 1] + b2[k + 1], 0.f) * w3[(k + 1) * 32 + j];
        }
        __shared__ float red2[8][32];
        red2[g][j] = a0 + a1;
        __syncthreads();
        if (tid < 32) {
            float tot = red2[0][j];
            #pragma unroll
            for (int gg = 1; gg < 8; gg++) tot += red2[gg][j];
            float h = fmaxf(tot + b3[j], 0.f);
            float p0 = h * wc[j * 2 + 0];
            float p1 = h * wc[j * 2 + 1];
            #pragma unroll
            for (int o = 16; o > 0; o >>= 1) {
                p0 += __shfl_xor_sync(0xffffffff, p0, o);
                p1 += __shfl_xor_sync(0xffffffff, p1, o);
            }
            if (j == 0) {
                float l0 = p0 + bc[0], l1 = p1 + bc[1];
                float m = fmaxf(l0, l1);
                float e0 = expf(l0 - m), e1 = expf(l1 - m);
                float s = e0 + e1;
                out[i * 2 + 0] = e0 / s;
                out[i * 2 + 1] = e1 / s;
            }
        }
        return;
    }

    // ---- gemm2: h2 += relu(h1+b1) @ w2; 16 ntiles x 8 kchunks of 128 ----
    const int KCHUNK = 128;
    int ntile = blk & 15;
    int k0 = (blk >> 4) * KCHUNK;

    __shared__ float As[16][132];
    __shared__ float Bs[16][68];
    int tx = tid & 15, ty = tid >> 4;
    int bk = tid >> 6;
    int bn = tid & 63;

    unsigned long long acc[8][2];
    #pragma unroll
    for (int m = 0; m < 8; m++) { acc[m][0] = 0ull; acc[m][1] = 0ull; }

    float ra[8], rb[4];
    #pragma unroll
    for (int p = 0; p < 8; p++) {
        int kg = k0 + tx;
        ra[p] = fmaxf(g_h1[(ty + p * 16) * DH + kg] + bias[kg], 0.f);
    }
    #pragma unroll
    for (int p = 0; p < 4; p++)
        rb[p] = B[(k0 + p * 4 + bk) * DH + ntile * 64 + bn];

    for (int kt = 0; kt < KCHUNK; kt += 16) {
        #pragma unroll
        for (int p = 0; p < 8; p++) As[tx][ty + p * 16] = ra[p];
        #pragma unroll
        for (int p = 0; p < 4; p++) Bs[p * 4 + bk][bn] = rb[p];
        __syncthreads();
        if (kt + 16 < KCHUNK) {
            int kg = k0 + kt + 16;
            #pragma unroll
            for (int p = 0; p < 8; p++)
                ra[p] = fmaxf(g_h1[(ty + p * 16) * DH + kg + tx] + bias[kg + tx], 0.f);
            #pragma unroll
            for (int p = 0; p < 4; p++)
                rb[p] = B[(kg + p * 4 + bk) * DH + ntile * 64 + bn];
        }
        #pragma unroll
        for (int kk = 0; kk < 16; kk++) {
            float4 a0 = *(const float4*)&As[kk][ty * 8];
            float4 a1 = *(const float4*)&As[kk][ty * 8 + 4];
            ulonglong2 bv = *(const ulonglong2*)&Bs[kk][tx * 4];
            float am[8] = {a0.x, a0.y, a0.z, a0.w, a1.x, a1.y, a1.z, a1.w};
            #pragma unroll
            for (int m = 0; m < 8; m++) {
                unsigned long long aa = pack_dup(am[m]);
                fma2(acc[m][0], aa, bv.x);
                fma2(acc[m][1], aa, bv.y);
            }
        }
        __syncthreads();
    }
    #pragma unroll
    for (int m = 0; m < 8; m++) {
        int r = ty * 8 + m;
        int n = ntile * 64 + tx * 4;
        float l0, h0, l1, h1v;
        unpack2(acc[m][0], l0, h0);
        unpack2(acc[m][1], l1, h1v);
        red4(&g_h2[r * DH + n], l0, h0, l1, h1v);
    }
    __threadfence();
    __syncthreads();
    if (tid == 0) atomicAdd(&g_flag4, 1);
}

// ---------------- launch ------------------------------------------------------
extern "C" void kernel_launch(void* const* d_in, const int* in_sizes, int n_in,
                              void* d_out, int out_size) {
    const float* pixfeat = (const float*)d_in[0];
    const float* w1 = (const float*)d_in[1];
    const float* b1 = (const float*)d_in[2];
    const float* w2 = (const float*)d_in[3];
    const float* b2 = (const float*)d_in[4];
    const float* w3 = (const float*)d_in[5];
    const float* b3 = (const float*)d_in[6];
    const float* wc = (const float*)d_in[7];
    const float* bc = (const float*)d_in[8];
    const int*   sp = (const int*)d_in[9];
    const int*   yy = (const int*)d_in[10];
    float* out = (float*)d_out;  // [0,256): probs, [256,384): lab

    k_prep<<<NS, 256>>>(sp, yy);                          // 1
    k_segsum<<<dim3(33, NS), 256>>>(pixfeat);             // 2
    k_gemm1_gram<<<450, 256>>>(w1);                       // 3
    k_gemm2_tail<<<257, 256>>>(w2, b1, b2, w3, b3, wc, bc, out);  // 4 <- profiled
}

// round 16
// speedup vs baseline: 1.0546x; 1.0193x over previous
#include <cuda_runtime.h>
#include <math.h>

#define NPIX 50176
#define CF   4224
#define NS   128
#define DH   1024
#define PPB  392
#define ROWQ (CF / 4)
#define SEGCAP 768

// ---------------- scratch ----------------------------------------------------
__device__ int   g_hist[NS];
__device__ int   g_off[NS + 1];
__device__ int   g_bh[NS * NS];
__device__ int   g_bcls[NS * NS * 3];
__device__ int   g_perm[NPIX];
__device__ int   g_lab[NS];
__device__ float g_feat[NS * CF];
__device__ float g_G[NS * NS];
__device__ float g_h1[NS * DH];
__device__ float g_h2[NS * DH];
__device__ int   g_bar0;
__device__ int   g_bar1;
__device__ int   g_flag4;    // gemm2 blocks done (target 256)

// ---------------- helpers ----------------------------------------------------
__device__ __forceinline__ unsigned long long pack_dup(float a) {
    unsigned long long r;
    asm("mov.b64 %0, {%1, %1};" : "=l"(r) : "f"(a));
    return r;
}
__device__ __forceinline__ void fma2(unsigned long long& acc,
                                     unsigned long long a,
                                     unsigned long long b) {
    asm("fma.rn.f32x2 %0, %1, %2, %0;" : "+l"(acc) : "l"(a), "l"(b));
}
__device__ __forceinline__ void unpack2(unsigned long long v, float& lo, float& hi) {
    asm("mov.b64 {%0, %1}, %2;" : "=f"(lo), "=f"(hi) : "l"(v));
}
__device__ __forceinline__ void red4(float* p, float a, float b, float c, float d) {
    asm volatile("red.global.add.v4.f32 [%0], {%1, %2, %3, %4};"
                 :: "l"(p), "f"(a), "f"(b), "f"(c), "f"(d) : "memory");
}
__device__ __forceinline__ void spin_for(const int* flag, int target) {
    if (threadIdx.x == 0) {
        while (*(volatile const int*)flag < target) __nanosleep(64);
    }
    __syncthreads();
    __threadfence();
}

// ---------------- K1: prep (hist + meta + scatter + zero) -------------------
__global__ void __launch_bounds__(256) k_prep(const int* __restrict__ sp,
                                              const int* __restrict__ y) {
    __shared__ int sh[NS];
    __shared__ int sc[NS * 3];
    __shared__ int cur[NS];
    int b = blockIdx.x;
    int tid = threadIdx.x;

    if (b == 0 && tid == 0) g_flag4 = 0;   // replay-deterministic reset

    for (int i = tid; i < NS; i += 256) sh[i] = 0;
    for (int i = tid; i < NS * 3; i += 256) sc[i] = 0;
    __syncthreads();
    int base = b * PPB;
    int s0 = sp[base + tid];
    int s1 = sp[base + 256 + ((tid < PPB - 256) ? tid : 0)];
    int y0 = y[base + tid];
    int y1 = y[base + 256 + ((tid < PPB - 256) ? tid : 0)];
    atomicAdd(&sh[s0], 1);
    atomicAdd(&sc[s0 * 3 + y0], 1);
    if (tid < PPB - 256) {
        atomicAdd(&sh[s1], 1);
        atomicAdd(&sc[s1 * 3 + y1], 1);
    }
    __syncthreads();
    for (int i = tid; i < NS; i += 256) g_bh[b * NS + i] = sh[i];
    for (int i = tid; i < NS * 3; i += 256) g_bcls[b * NS * 3 + i] = sc[i];

    float4 z = make_float4(0.f, 0.f, 0.f, 0.f);
    ((float4*)g_h1)[b * 256 + tid] = z;
    ((float4*)g_h2)[b * 256 + tid] = z;
    if (tid < 32) ((float4*)g_G)[b * 32 + tid] = z;

    __threadfence();
    __syncthreads();
    if (tid == 0) {
        atomicAdd(&g_bar0, 1);
        while (*(volatile int*)&g_bar0 < NS) { }
    }
    __syncthreads();

    __shared__ int off_sh[NS];
    __shared__ int tot_sh[NS];
    __shared__ int pre_sh[NS];
    if (tid < NS) {
        int s = tid;
        int tot = 0, pre = 0;
        for (int bb = 0; bb < NS; bb++) {
            int v = g_bh[bb * NS + s];
            if (bb < b) pre += v;
            tot += v;
        }
        tot_sh[s] = tot;
        pre_sh[s] = pre;
        if (b == 0) {
            g_hist[s] = tot;
            int c0 = 0, c1 = 0, c2 = 0;
            for (int bb = 0; bb < NS; bb++) {
                c0 += g_bcls[bb * NS * 3 + s * 3 + 0];
                c1 += g_bcls[bb * NS * 3 + s * 3 + 1];
                c2 += g_bcls[bb * NS * 3 + s * 3 + 2];
            }
            int lab = (c1 > c0) ? ((c2 > c1) ? 2 : 1) : ((c2 > c0) ? 2 : 0);
            if (lab == 0) lab = (c2 > (tot >> 1)) ? 2 : ((c1 >= 1) ? 1 : 0);
            g_lab[s] = lab;
        }
    }
    __syncthreads();
    if (tid == 0) {
        int a = 0;
        for (int i = 0; i < NS; i++) { off_sh[i] = a; a += tot_sh[i]; }
        if (b == 0) {
            for (int i = 0; i < NS; i++) g_off[i] = off_sh[i];
            g_off[NS] = a;
        }
    }
    __syncthreads();
    if (tid < NS) cur[tid] = off_sh[tid] + pre_sh[tid];
    __syncthreads();

    {
        int p = atomicAdd(&cur[s0], 1);
        g_perm[p] = base + tid;
        if (tid < PPB - 256) {
            int q = atomicAdd(&cur[s1], 1);
            g_perm[q] = base + 256 + tid;
        }
    }

    __threadfence();
    __syncthreads();
    if (tid == 0) {
        int v = atomicAdd(&g_bar1, 1);
        if (v == NS - 1) { g_bar0 = 0; g_bar1 = 0; }
    }
}

// ---------------- K2: segment mean (~84% DRAM; unchanged) -------------------
__global__ void __launch_bounds__(256) k_segsum(const float* __restrict__ pix) {
    int ct = blockIdx.x;
    int s  = blockIdx.y;
    int tx = threadIdx.x & 31;
    int ty = threadIdx.x >> 5;
    int beg = g_off[s], end = g_off[s + 1];
    int n = end - beg;

    __shared__ int sidx[SEGCAP];
    int cap = n < SEGCAP ? n : SEGCAP;
    for (int i = threadIdx.x; i < cap; i += 256) sidx[i] = g_perm[beg + i];
    __syncthreads();

    const float4* __restrict__ p4 = (const float4*)pix;
    int colq = ct * 32 + tx;

    float4 A0 = make_float4(0.f, 0.f, 0.f, 0.f);
    float4 A1 = make_float4(0.f, 0.f, 0.f, 0.f);
    float4 A2 = make_float4(0.f, 0.f, 0.f, 0.f);
    float4 A3 = make_float4(0.f, 0.f, 0.f, 0.f);

    int r = ty;
    for (; r + 56 < cap; r += 64) {
        float4 v0 = __ldcs(p4 + (size_t)sidx[r]      * ROWQ + colq);
        float4 v1 = __ldcs(p4 + (size_t)sidx[r +  8] * ROWQ + colq);
        float4 v2 = __ldcs(p4 + (size_t)sidx[r + 16] * ROWQ + colq);
        float4 v3 = __ldcs(p4 + (size_t)sidx[r + 24] * ROWQ + colq);
        float4 v4 = __ldcs(p4 + (size_t)sidx[r + 32] * ROWQ + colq);
        float4 v5 = __ldcs(p4 + (size_t)sidx[r + 40] * ROWQ + colq);
        float4 v6 = __ldcs(p4 + (size_t)sidx[r + 48] * ROWQ + colq);
        float4 v7 = __ldcs(p4 + (size_t)sidx[r + 56] * ROWQ + colq);
        A0.x += v0.x; A0.y += v0.y; A0.z += v0.z; A0.w += v0.w;
        A1.x += v1.x; A1.y += v1.y; A1.z += v1.z; A1.w += v1.w;
        A2.x += v2.x; A2.y += v2.y; A2.z += v2.z; A2.w += v2.w;
        A3.x += v3.x; A3.y += v3.y; A3.z += v3.z; A3.w += v3.w;
        A0.x += v4.x; A0.y += v4.y; A0.z += v4.z; A0.w += v4.w;
        A1.x += v5.x; A1.y += v5.y; A1.z += v5.z; A1.w += v5.w;
        A2.x += v6.x; A2.y += v6.y; A2.z += v6.z; A2.w += v6.w;
        A3.x += v7.x; A3.y += v7.y; A3.z += v7.z; A3.w += v7.w;
    }
    for (; r < cap; r += 8) {
        float4 v0 = __ldcs(p4 + (size_t)sidx[r] * ROWQ + colq);
        A0.x += v0.x; A0.y += v0.y; A0.z += v0.z; A0.w += v0.w;
    }
    for (int r2 = SEGCAP + ty; r2 < n; r2 += 8) {
        float4 v0 = __ldcs(p4 + (size_t)g_perm[beg + r2] * ROWQ + colq);
        A0.x += v0.x; A0.y += v0.y; A0.z += v0.z; A0.w += v0.w;
    }
    A0.x += A1.x + A2.x + A3.x;
    A0.y += A1.y + A2.y + A3.y;
    A0.z += A1.z + A2.z + A3.z;
    A0.w += A1.w + A2.w + A3.w;

    __shared__ float4 red[8][32];
    red[ty][tx] = A0;
    __syncthreads();
    if (ty == 0) {
        float4 t = red[0][tx];
        #pragma unroll
        for (int w = 1; w < 8; w++) {
            t.x += red[w][tx].x; t.y += red[w][tx].y;
            t.z += red[w][tx].z; t.w += red[w][tx].w;
        }
        float c = (float)max(n, 1);
        t.x /= c; t.y /= c; t.z /= c; t.w /= c;
        *(float4*)&g_feat[s * CF + colq * 4] = t;
    }
}

// ---------------- K3: gemm1 (384 blocks, kchunk 176, dbl-buf) + gram (66) ---
__global__ void __launch_bounds__(256) k_gemm1_gram(const float* __restrict__ B) {
    int blk = blockIdx.x;
    int tid = threadIdx.x;

    if (blk >= 384) {
        // ---- gram: G += feat_chunk @ feat_chunk^T ----
        __shared__ float Gs[64][129];
        int kc = blk - 384;  // 0..65
        {
            int k  = tid & 63;
            int io = tid >> 6;
            #pragma unroll 8
            for (int p = 0; p < 32; p++) {
                int i = p * 4 + io;
                Gs[k][i] = g_feat[i * CF + kc * 64 + k];
            }
        }
        __syncthreads();
        int tx = tid & 15, ty = tid >> 4;
        float acc[8][8];
        #pragma unroll
        for (int m = 0; m < 8; m++)
            #pragma unroll
            for (int n = 0; n < 8; n++) acc[m][n] = 0.f;
        for (int kk = 0; kk < 64; kk++) {
            float a[8], b[8];
            #pragma unroll
            for (int m = 0; m < 8; m++) a[m] = Gs[kk][ty * 8 + m];
            #pragma unroll
            for (int n = 0; n < 8; n++) b[n] = Gs[kk][tx * 8 + n];
            #pragma unroll
            for (int m = 0; m < 8; m++)
                #pragma unroll
                for (int n = 0; n < 8; n++) acc[m][n] += a[m] * b[n];
        }
        #pragma unroll
        for (int m = 0; m < 8; m++) {
            float* dst = &g_G[(ty * 8 + m) * NS + tx * 8];
            red4(dst,     acc[m][0], acc[m][1], acc[m][2], acc[m][3]);
            red4(dst + 4, acc[m][4], acc[m][5], acc[m][6], acc[m][7]);
        }
        return;
    }

    // ---- gemm1: h1 += feat @ w1; 16 ntiles x 24 kchunks of 176 ----
    const int KCHUNK = 176;
    int ntile = blk & 15;
    int k0 = (blk >> 4) * KCHUNK;

    __shared__ float As[16][132];
    __shared__ float Bs[16][68];
    int tx = tid & 15, ty = tid >> 4;
    int bk = tid >> 6;       // 0..3
    int bn = tid & 63;

    unsigned long long acc[8][2];
    #pragma unroll
    for (int m = 0; m < 8; m++) { acc[m][0] = 0ull; acc[m][1] = 0ull; }

    float ra[8], rb[4];
    #pragma unroll
    for (int p = 0; p < 8; p++)
        ra[p] = g_feat[(ty + p * 16) * CF + k0 + tx];
    #pragma unroll
    for (int p = 0; p < 4; p++)
        rb[p] = B[(k0 + p * 4 + bk) * DH + ntile * 64 + bn];

    for (int kt = 0; kt < KCHUNK; kt += 16) {
        #pragma unroll
        for (int p = 0; p < 8; p++) As[tx][ty + p * 16] = ra[p];
        #pragma unroll
        for (int p = 0; p < 4; p++) Bs[p * 4 + bk][bn] = rb[p];
        __syncthreads();
        if (kt + 16 < KCHUNK) {   // prefetch next slab during compute
            int kg = k0 + kt + 16;
            #pragma unroll
            for (int p = 0; p < 8; p++)
                ra[p] = g_feat[(ty + p * 16) * CF + kg + tx];
            #pragma unroll
            for (int p = 0; p < 4; p++)
                rb[p] = B[(kg + p * 4 + bk) * DH + ntile * 64 + bn];
        }
        #pragma unroll
        for (int kk = 0; kk < 16; kk++) {
            float4 a0 = *(const float4*)&As[kk][ty * 8];
            float4 a1 = *(const float4*)&As[kk][ty * 8 + 4];
            ulonglong2 bv = *(const ulonglong2*)&Bs[kk][tx * 4];
            float am[8] = {a0.x, a0.y, a0.z, a0.w, a1.x, a1.y, a1.z, a1.w};
            #pragma unroll
            for (int m = 0; m < 8; m++) {
                unsigned long long aa = pack_dup(am[m]);
                fma2(acc[m][0], aa, bv.x);
                fma2(acc[m][1], aa, bv.y);
            }
        }
        __syncthreads();
    }
    #pragma unroll
    for (int m = 0; m < 8; m++) {
        int r = ty * 8 + m;
        int n = ntile * 64 + tx * 4;
        float l0, h0, l1, h1v;
        unpack2(acc[m][0], l0, h0);
        unpack2(acc[m][1], l1, h1v);
        red4(&g_h1[r * DH + n], l0, h0, l1, h1v);
    }
}

// ---------------- K4: gemm2 (256 blocks, kchunk 64) + labels + tail ---------
// 385 blocks, <=80 regs -> ~3 blocks/SM -> all co-resident; spin is safe.
__global__ void __launch_bounds__(256) k_gemm2_tail(const float* __restrict__ B,
                               const float* __restrict__ bias,
                               const float* __restrict__ b2,
                               const float* __restrict__ w3,
                               const float* __restrict__ b3,
                               const float* __restrict__ wc,
                               const float* __restrict__ bc,
                               float* __restrict__ out) {
    int blk = blockIdx.x;
    int tid = threadIdx.x;

    if (blk == 256) {
        // ---- label propagation ----
        __shared__ float nrm[NS];
        __shared__ int   labsh[NS];
        int i = tid;
        if (i < NS) {
            labsh[i] = g_lab[i];
            nrm[i] = rsqrtf(g_G[i * NS + i]);
        }
        __syncthreads();
        if (i < NS) {
            float maxv = -__int_as_float(0x7f800000);
            int best = 0;
            float ni = nrm[i];
            for (int j = 0; j < NS; j++) {
                if (labsh[j] != 0) {
                    float a = g_G[i * NS + j] * ni * nrm[j];
                    if (a > maxv) { maxv = a; best = j; }
                }
            }
            int lab = labsh[i];
            if (lab == 0 && maxv > 0.8f) lab = labsh[best];
            out[256 + i] = (float)lab;
        }
        return;
    }

    if (blk > 256) {
        // ---- tail: h3 = relu(h2+b2)@w3, head, softmax (after gemm2) ----
        spin_for(&g_flag4, 256);
        int i = blk - 257;
        int j = tid & 31;
        int g = tid >> 5;
        const float* __restrict__ h2r = g_h2 + i * DH;
        float a0 = 0.f, a1 = 0.f;
        int kbase = g * 128;
        #pragma unroll 4
        for (int kk = 0; kk < 128; kk += 2) {
            int k = kbase + kk;
            a0 += fmaxf(h2r[k] + b2[k], 0.f) * w3[k * 32 + j];
            a1 += fmaxf(h2r[k + 1] + b2[k + 1], 0.f) * w3[(k + 1) * 32 + j];
        }
        __shared__ float red2[8][32];
        red2[g][j] = a0 + a1;
        __syncthreads();
        if (tid < 32) {
            float tot = red2[0][j];
            #pragma unroll
            for (int gg = 1; gg < 8; gg++) tot += red2[gg][j];
            float h = fmaxf(tot + b3[j], 0.f);
            float p0 = h * wc[j * 2 + 0];
            float p1 = h * wc[j * 2 + 1];
            #pragma unroll
            for (int o = 16; o > 0; o >>= 1) {
                p0 += __shfl_xor_sync(0xffffffff, p0, o);
                p1 += __shfl_xor_sync(0xffffffff, p1, o);
            }
            if (j == 0) {
                float l0 = p0 + bc[0], l1 = p1 + bc[1];
                float m = fmaxf(l0, l1);
                float e0 = expf(l0 - m), e1 = expf(l1 - m);
                float s = e0 + e1;
                out[i * 2 + 0] = e0 / s;
                out[i * 2 + 1] = e1 / s;
            }
        }
        return;
    }

    // ---- gemm2: h2 += relu(h1+b1) @ w2; 16 ntiles x 16 kchunks of 64 ----
    const int KCHUNK = 64;
    int ntile = blk & 15;
    int k0 = (blk >> 4) * KCHUNK;

    __shared__ float As[16][132];
    __shared__ float Bs[16][68];
    int tx = tid & 15, ty = tid >> 4;
    int bk = tid >> 6;
    int bn = tid & 63;

    unsigned long long acc[8][2];
    #pragma unroll
    for (int m = 0; m < 8; m++) { acc[m][0] = 0ull; acc[m][1] = 0ull; }

    float ra[8], rb[4];
    #pragma unroll
    for (int p = 0; p < 8; p++) {
        int kg = k0 + tx;
        ra[p] = fmaxf(g_h1[(ty + p * 16) * DH + kg] + bias[kg], 0.f);
    }
    #pragma unroll
    for (int p = 0; p < 4; p++)
        rb[p] = B[(k0 + p * 4 + bk) * DH + ntile * 64 + bn];

    for (int kt = 0; kt < KCHUNK; kt += 16) {
        #pragma unroll
        for (int p = 0; p < 8; p++) As[tx][ty + p * 16] = ra[p];
        #pragma unroll
        for (int p = 0; p < 4; p++) Bs[p * 4 + bk][bn] = rb[p];
        __syncthreads();
        if (kt + 16 < KCHUNK) {
            int kg = k0 + kt + 16;
            #pragma unroll
            for (int p = 0; p < 8; p++)
                ra[p] = fmaxf(g_h1[(ty + p * 16) * DH + kg + tx] + bias[kg + tx], 0.f);
            #pragma unroll
            for (int p = 0; p < 4; p++)
                rb[p] = B[(kg + p * 4 + bk) * DH + ntile * 64 + bn];
        }
        #pragma unroll
        for (int kk = 0; kk < 16; kk++) {
            float4 a0 = *(const float4*)&As[kk][ty * 8];
            float4 a1 = *(const float4*)&As[kk][ty * 8 + 4];
            ulonglong2 bv = *(const ulonglong2*)&Bs[kk][tx * 4];
            float am[8] = {a0.x, a0.y, a0.z, a0.w, a1.x, a1.y, a1.z, a1.w};
            #pragma unroll
            for (int m = 0; m < 8; m++) {
                unsigned long long aa = pack_dup(am[m]);
                fma2(acc[m][0], aa, bv.x);
                fma2(acc[m][1], aa, bv.y);
            }
        }
        __syncthreads();
    }
    #pragma unroll
    for (int m = 0; m < 8; m++) {
        int r = ty * 8 + m;
        int n = ntile * 64 + tx * 4;
        float l0, h0, l1, h1v;
        unpack2(acc[m][0], l0, h0);
        unpack2(acc[m][1], l1, h1v);
        red4(&g_h2[r * DH + n], l0, h0, l1, h1v);
    }
    __threadfence();
    __syncthreads();
    if (tid == 0) atomicAdd(&g_flag4, 1);
}

// ---------------- launch ------------------------------------------------------
extern "C" void kernel_launch(void* const* d_in, const int* in_sizes, int n_in,
                              void* d_out, int out_size) {
    const float* pixfeat = (const float*)d_in[0];
    const float* w1 = (const float*)d_in[1];
    const float* b1 = (const float*)d_in[2];
    const float* w2 = (const float*)d_in[3];
    const float* b2 = (const float*)d_in[4];
    const float* w3 = (const float*)d_in[5];
    const float* b3 = (const float*)d_in[6];
    const float* wc = (const float*)d_in[7];
    const float* bc = (const float*)d_in[8];
    const int*   sp = (const int*)d_in[9];
    const int*   yy = (const int*)d_in[10];
    float* out = (float*)d_out;  // [0,256): probs, [256,384): lab

    k_prep<<<NS, 256>>>(sp, yy);                          // 1
    k_segsum<<<dim3(33, NS), 256>>>(pixfeat);             // 2
    k_gemm1_gram<<<450, 256>>>(w1);                       // 3
    k_gemm2_tail<<<385, 256>>>(w2, b1, b2, w3, b3, wc, bc, out);  // 4 <- profiled
}